// round 7
// baseline (speedup 1.0000x reference)
#include <cuda_runtime.h>
#include <cuda_bf16.h>
#include <math.h>
#include <stdint.h>

#define NTOK 8192
#define DDIM 1024
#define HDIM 4096
#define NEXP 8
#define NASSIGN (NTOK*2)

// ---------------- scratch (device globals; no allocation) ----------------
__device__ float g_h[(size_t)NASSIGN * HDIM];      // fp32 hidden
__device__ float g_loadc[NTOK * NEXP];
__device__ int   g_route_e[NASSIGN];
__device__ float g_route_g[NASSIGN];
__device__ int   g_counts[NEXP];
__device__ int   g_perm[NEXP * NTOK];
__device__ float g_load[NEXP];
__device__ float g_imp[NEXP];
// int8 limbs + scales
__device__ char  g_xq1[(size_t)NTOK * DDIM];
__device__ char  g_xq2[(size_t)NTOK * DDIM];
__device__ float g_sx[NTOK];
__device__ char  g_hq1[(size_t)NASSIGN * HDIM];
__device__ char  g_hq2[(size_t)NASSIGN * HDIM];
__device__ float g_sh[NASSIGN];
// weights transposed to [e][n][k] int8 limbs
__device__ char  g_w1q1[(size_t)NEXP * HDIM * DDIM];
__device__ char  g_w1q2[(size_t)NEXP * HDIM * DDIM];
__device__ float g_sw1[NEXP * HDIM];
__device__ char  g_w2q1[(size_t)NEXP * DDIM * HDIM];
__device__ char  g_w2q2[(size_t)NEXP * DDIM * HDIM];
__device__ float g_sw2[NEXP * DDIM];

// ---------------- helpers ----------------
__device__ __forceinline__ uint32_t smem_to_u32(const void* p) {
    uint32_t a;
    asm("{ .reg .u64 t; cvta.to.shared.u64 t, %1; cvt.u32.u64 %0, t; }" : "=r"(a) : "l"(p));
    return a;
}
__device__ __forceinline__ void ldsm4(uint32_t* r, uint32_t a) {
    asm volatile("ldmatrix.sync.aligned.m8n8.x4.shared.b16 {%0,%1,%2,%3}, [%4];"
        : "=r"(r[0]), "=r"(r[1]), "=r"(r[2]), "=r"(r[3]) : "r"(a));
}
__device__ __forceinline__ void imma16832(int* c, const uint32_t* a, const uint32_t* b) {
    asm volatile("mma.sync.aligned.m16n8k32.row.col.s32.s8.s8.s32 "
        "{%0,%1,%2,%3}, {%4,%5,%6,%7}, {%8,%9}, {%0,%1,%2,%3};"
        : "+r"(c[0]), "+r"(c[1]), "+r"(c[2]), "+r"(c[3])
        : "r"(a[0]), "r"(a[1]), "r"(a[2]), "r"(a[3]), "r"(b[0]), "r"(b[1]));
}
#define CP_ASYNC16(dst, src, sz) \
    asm volatile("cp.async.cg.shared.global [%0], [%1], 16, %2;" \
        :: "r"(dst), "l"(src), "r"(sz) : "memory")
#define CP_COMMIT() asm volatile("cp.async.commit_group;" ::: "memory")
#define CP_WAIT2()  asm volatile("cp.async.wait_group 2;" ::: "memory")

// ---------------- zero counters ----------------
__global__ void zero_counts() {
    if (threadIdx.x < NEXP) g_counts[threadIdx.x] = 0;
}
__global__ void zero_y(float4* __restrict__ y) {
    y[blockIdx.x * 256 + threadIdx.x] = make_float4(0.f, 0.f, 0.f, 0.f);
}

// ---------------- gating ----------------
__global__ void gate_kernel(const float* __restrict__ x,
                            const float* __restrict__ noise,
                            const float* __restrict__ wg,
                            const float* __restrict__ wn) {
    int warp = threadIdx.x >> 5;
    int lane = threadIdx.x & 31;
    int n = blockIdx.x * 8 + warp;
    if (n >= NTOK) return;
    float ac[8] = {0,0,0,0,0,0,0,0};
    float an[8] = {0,0,0,0,0,0,0,0};
    const float* xr = x + (size_t)n * DDIM;
    for (int d = lane; d < DDIM; d += 32) {
        float xv = xr[d];
        const float4* wgp = (const float4*)(wg + (size_t)d * 8);
        const float4* wnp = (const float4*)(wn + (size_t)d * 8);
        float4 gA = wgp[0], gB = wgp[1];
        float4 nA = wnp[0], nB = wnp[1];
        ac[0] += xv * gA.x; ac[1] += xv * gA.y; ac[2] += xv * gA.z; ac[3] += xv * gA.w;
        ac[4] += xv * gB.x; ac[5] += xv * gB.y; ac[6] += xv * gB.z; ac[7] += xv * gB.w;
        an[0] += xv * nA.x; an[1] += xv * nA.y; an[2] += xv * nA.z; an[3] += xv * nA.w;
        an[4] += xv * nB.x; an[5] += xv * nB.y; an[6] += xv * nB.z; an[7] += xv * nB.w;
    }
    #pragma unroll
    for (int off = 16; off; off >>= 1)
        #pragma unroll
        for (int e = 0; e < 8; e++) {
            ac[e] += __shfl_xor_sync(0xffffffffu, ac[e], off);
            an[e] += __shfl_xor_sync(0xffffffffu, an[e], off);
        }
    if (lane == 0) {
        float clean[8], sd[8], nz[8];
        #pragma unroll
        for (int e = 0; e < 8; e++) {
            clean[e] = ac[e];
            float z = an[e];
            float sp = fmaxf(z, 0.0f) + log1pf(expf(-fabsf(z)));
            sd[e] = sp + 0.01f;
            nz[e] = clean[e] + noise[(size_t)n * 8 + e] * sd[e];
        }
        int i0 = 0, i1 = -1;
        float v0 = nz[0], v1 = -INFINITY, v2 = -INFINITY;
        #pragma unroll
        for (int e = 1; e < 8; e++) {
            float v = nz[e];
            if (v > v0)      { v2 = v1; v1 = v0; i1 = i0; v0 = v; i0 = e; }
            else if (v > v1) { v2 = v1; v1 = v;  i1 = e; }
            else if (v > v2) { v2 = v; }
        }
        float t = expf(v1 - v0);
        float gate0 = 1.0f / (1.0f + t);
        float gate1 = t / (1.0f + t);
        #pragma unroll
        for (int e = 0; e < 8; e++) {
            bool is_in = nz[e] > v2;
            float thr = is_in ? v2 : v1;
            g_loadc[(size_t)n * 8 + e] = normcdff((clean[e] - thr) / sd[e]);
        }
        g_route_e[2 * n]     = i0;  g_route_g[2 * n]     = gate0;
        g_route_e[2 * n + 1] = i1;  g_route_g[2 * n + 1] = gate1;
        int p0 = atomicAdd(&g_counts[i0], 1);
        g_perm[i0 * NTOK + p0] = 2 * n;
        int p1 = atomicAdd(&g_counts[i1], 1);
        g_perm[i1 * NTOK + p1] = 2 * n + 1;
    }
}

__global__ void reduce_kernel() {
    int e = blockIdx.x;
    int t = threadIdx.x;
    float sl = 0.0f, si = 0.0f;
    for (int n = t; n < NTOK; n += 256) sl += g_loadc[(size_t)n * 8 + e];
    for (int a = t; a < NASSIGN; a += 256)
        if (g_route_e[a] == e) si += g_route_g[a];
    __shared__ float shl[256], shi[256];
    shl[t] = sl; shi[t] = si;
    __syncthreads();
    for (int off = 128; off; off >>= 1) {
        if (t < off) { shl[t] += shl[t + off]; shi[t] += shi[t + off]; }
        __syncthreads();
    }
    if (t == 0) { g_load[e] = shl[0]; g_imp[e] = shi[0]; }
}

__global__ void loss_kernel(float* __restrict__ out) {
    if (threadIdx.x != 0 || blockIdx.x != 0) return;
    float mi = 0.0f, ml = 0.0f;
    for (int e = 0; e < NEXP; e++) { mi += g_imp[e]; ml += g_load[e]; }
    mi *= (1.0f / NEXP); ml *= (1.0f / NEXP);
    float vi = 0.0f, vl = 0.0f;
    for (int e = 0; e < NEXP; e++) {
        float di = g_imp[e] - mi;  vi += di * di;
        float dl = g_load[e] - ml; vl += dl * dl;
    }
    vi *= (1.0f / (NEXP - 1)); vl *= (1.0f / (NEXP - 1));
    out[0] = (vi / (mi * mi + 1e-10f) + vl / (ml * ml + 1e-10f)) * 0.01f;
}

// ---------------- per-row 2-limb int8 quantization ----------------
__global__ void quantize_rows(const float* __restrict__ src,
                              char* __restrict__ q1, char* __restrict__ q2,
                              float* __restrict__ scale, int C) {
    int row = blockIdx.x;
    int t = threadIdx.x;
    const float* r = src + (size_t)row * C;
    float mx = 0.0f;
    for (int i = t; i < C; i += 256) mx = fmaxf(mx, fabsf(r[i]));
    __shared__ float red[256];
    red[t] = mx;
    __syncthreads();
    for (int off = 128; off; off >>= 1) {
        if (t < off) red[t] = fmaxf(red[t], red[t + off]);
        __syncthreads();
    }
    float m = fmaxf(red[0], 1e-20f);
    float s = m * (1.0f / 127.0f);
    float inv = 127.0f / m;
    float inv2 = 254.0f / s;
    if (t == 0) scale[row] = s;
    for (int i = t * 4; i < C; i += 1024) {
        float4 v = *(const float4*)(r + i);
        float a1x = rintf(v.x * inv), a1y = rintf(v.y * inv),
              a1z = rintf(v.z * inv), a1w = rintf(v.w * inv);
        char4 c1 = make_char4((char)(int)a1x, (char)(int)a1y, (char)(int)a1z, (char)(int)a1w);
        char4 c2 = make_char4(
            (char)(int)rintf((v.x - a1x * s) * inv2),
            (char)(int)rintf((v.y - a1y * s) * inv2),
            (char)(int)rintf((v.z - a1z * s) * inv2),
            (char)(int)rintf((v.w - a1w * s) * inv2));
        *(char4*)(q1 + (size_t)row * C + i) = c1;
        *(char4*)(q2 + (size_t)row * C + i) = c2;
    }
}

// ---------------- fused weight colmax + quantize + transpose ----------------
// block = 32-column strip x full K; pass1 colmax (DRAM), pass2 quantize (L2 hits).
__global__ void quant_w_fused(const float* __restrict__ W, float* __restrict__ swout,
                              char* __restrict__ q1, char* __restrict__ q2,
                              int K, int N) {
    int e = blockIdx.y;
    int n0 = blockIdx.x * 32;
    int tx = threadIdx.x & 31;
    int ty = threadIdx.x >> 5;     // 0..7
    const float* Wp = W + (size_t)e * K * N + n0;

    float mx = 0.0f;
    for (int k = ty; k < K; k += 8)
        mx = fmaxf(mx, fabsf(Wp[(size_t)k * N + tx]));
    __shared__ float red[8][33];
    __shared__ float colmax[32];
    red[ty][tx] = mx;
    __syncthreads();
    if (ty == 0) {
        float m = red[0][tx];
        #pragma unroll
        for (int i = 1; i < 8; i++) m = fmaxf(m, red[i][tx]);
        m = fmaxf(m, 1e-20f);
        colmax[tx] = m;
        swout[(size_t)e * N + n0 + tx] = m * (1.0f / 127.0f);
    }
    __syncthreads();

    __shared__ float tile[32][33];
    for (int k0 = 0; k0 < K; k0 += 32) {
        #pragma unroll
        for (int i = 0; i < 4; i++)
            tile[ty + 8 * i][tx] = Wp[(size_t)(k0 + ty + 8 * i) * N + tx];
        __syncthreads();
        #pragma unroll
        for (int i = 0; i < 4; i++) {
            int nn = ty + 8 * i;
            float v = tile[tx][nn];               // W[k0+tx][n0+nn]
            float m = colmax[nn];
            float s = m * (1.0f / 127.0f);
            float a1 = rintf(v * (127.0f / m));
            float a2 = rintf((v - a1 * s) * (254.0f / s));
            size_t o = ((size_t)e * N + n0 + nn) * K + k0 + tx;
            q1[o] = (char)(int)a1;
            q2[o] = (char)(int)a2;
        }
        __syncthreads();
    }
}

// ---------------- int8 limb grouped expert GEMM ----------------
// CTA 128x128, k-chunk 64 bytes, 8 warps (2m x 4n), warp tile 64x32, 4-stage pipe.
// Stage: A1@0 (8K) | A2@8192 | B1@16384 | B2@24576 = 32KB.
// Mainloop issues the 3 limb terms in 3 separate passes so no two consecutive
// IMMAs share an accumulator (MMA latency hidden by 16 independent ops).
#define STG 32768
#define NSTAGE 4
#define GEMM_SMEM (NSTAGE * STG)

template <int WHICH>
__global__ __launch_bounds__(256, 1) void moe_gemm_i8(const float* __restrict__ bias,
                                                      float* __restrict__ yout) {
    constexpr int KD = WHICH ? HDIM : DDIM;
    constexpr int NC = WHICH ? DDIM : HDIM;
    constexpr int NST = KD / 64;

    const int e = blockIdx.z;
    const int count = g_counts[e];
    const int m0 = blockIdx.y * 128;
    if (m0 >= count) return;
    const int c0 = blockIdx.x * 128;

    extern __shared__ char smem[];
    __shared__ int s_a[128];
    const uint32_t sb = smem_to_u32(smem);
    const int t = threadIdx.x;
    const int lane = t & 31, wid = t >> 5;
    const int wm = wid & 1, wn = wid >> 1;

    if (t < 128) {
        int m = m0 + t;
        s_a[t] = (m < count) ? g_perm[e * NTOK + m] : -1;
    }
    __syncthreads();

    const char* Aq1 = WHICH ? g_hq1 : g_xq1;
    const char* Aq2 = WHICH ? g_hq2 : g_xq2;
    const char* Bq1 = (WHICH ? g_w2q1 : g_w1q1) + ((size_t)e * NC + c0) * KD;
    const char* Bq2 = (WHICH ? g_w2q2 : g_w1q2) + ((size_t)e * NC + c0) * KD;

    const char *sA1[2], *sA2[2];
    uint32_t adst[2]; int asz[2];
    #pragma unroll
    for (int i = 0; i < 2; i++) {
        int u = t + 256 * i;
        int r = u >> 2, c = u & 3;
        int a = s_a[r];
        int rowi = (a < 0) ? 0 : (WHICH ? a : (a >> 1));
        sA1[i] = Aq1 + (size_t)rowi * KD + c * 16;
        sA2[i] = Aq2 + (size_t)rowi * KD + c * 16;
        asz[i] = (a < 0) ? 0 : 16;
        adst[i] = r * 64 + (((uint32_t)(c ^ (r & 3))) << 4);
    }
    const char *sB1[2], *sB2[2];
    uint32_t bdst[2];
    #pragma unroll
    for (int i = 0; i < 2; i++) {
        int u = t + 256 * i;
        int r = u >> 2, c = u & 3;
        sB1[i] = Bq1 + (size_t)r * KD + c * 16;
        sB2[i] = Bq2 + (size_t)r * KD + c * 16;
        bdst[i] = r * 64 + (((uint32_t)(c ^ (r & 3))) << 4);
    }

    auto load_stage = [&](int s) {
        uint32_t base = sb + (uint32_t)(s & (NSTAGE - 1)) * STG;
        int koff = s * 64;
        #pragma unroll
        for (int i = 0; i < 2; i++) {
            CP_ASYNC16(base + adst[i],           sA1[i] + koff, asz[i]);
            CP_ASYNC16(base + 8192u + adst[i],   sA2[i] + koff, asz[i]);
            CP_ASYNC16(base + 16384u + bdst[i],  sB1[i] + koff, 16);
            CP_ASYNC16(base + 24576u + bdst[i],  sB2[i] + koff, 16);
        }
        CP_COMMIT();
    };

    const int g = lane >> 3, r8 = lane & 7;
    uint32_t aoff[4];
    #pragma unroll
    for (int mi = 0; mi < 4; mi++) {
        int row = wm * 64 + mi * 16 + (g & 1) * 8 + r8;
        int c = g >> 1;
        aoff[mi] = row * 64 + (((uint32_t)(c ^ (row & 3))) << 4);
    }
    uint32_t boff[2];
    #pragma unroll
    for (int nj = 0; nj < 2; nj++) {
        int row = wn * 32 + nj * 16 + (g >> 1) * 8 + r8;
        int c = g & 1;
        boff[nj] = 16384u + row * 64 + (((uint32_t)(c ^ (row & 3))) << 4);
    }

    int accM[4][4][4], accC[4][4][4];
    #pragma unroll
    for (int i = 0; i < 4; i++)
        #pragma unroll
        for (int j = 0; j < 4; j++)
            #pragma unroll
            for (int k = 0; k < 4; k++) { accM[i][j][k] = 0; accC[i][j][k] = 0; }

    load_stage(0);
    load_stage(1);
    load_stage(2);

    for (int s = 0; s < NST; s++) {
        CP_WAIT2();
        __syncthreads();
        if (s + 3 < NST) load_stage(s + 3);
        else CP_COMMIT();
        uint32_t ab = sb + (uint32_t)(s & (NSTAGE - 1)) * STG;
        #pragma unroll
        for (int ks = 0; ks < 2; ks++) {
            const uint32_t kx = (uint32_t)ks << 5;
            uint32_t A1f[4][4], A2f[4][4], B1f[2][4], B2f[2][4];
            #pragma unroll
            for (int mi = 0; mi < 4; mi++) {
                ldsm4(A1f[mi], ab + (aoff[mi] ^ kx));
                ldsm4(A2f[mi], ab + 8192u + (aoff[mi] ^ kx));
            }
            #pragma unroll
            for (int nj = 0; nj < 2; nj++) {
                ldsm4(B1f[nj], ab + (boff[nj] ^ kx));
                ldsm4(B2f[nj], ab + 8192u + (boff[nj] ^ kx));
            }
            // pass 1: accM += A1*B1
            #pragma unroll
            for (int nj = 0; nj < 2; nj++)
                #pragma unroll
                for (int half = 0; half < 2; half++) {
                    int n = nj * 2 + half;
                    #pragma unroll
                    for (int mi = 0; mi < 4; mi++)
                        imma16832(accM[mi][n], A1f[mi], &B1f[nj][half * 2]);
                }
            // pass 2: accC += A1*B2
            #pragma unroll
            for (int nj = 0; nj < 2; nj++)
                #pragma unroll
                for (int half = 0; half < 2; half++) {
                    int n = nj * 2 + half;
                    #pragma unroll
                    for (int mi = 0; mi < 4; mi++)
                        imma16832(accC[mi][n], A1f[mi], &B2f[nj][half * 2]);
                }
            // pass 3: accC += A2*B1
            #pragma unroll
            for (int nj = 0; nj < 2; nj++)
                #pragma unroll
                for (int half = 0; half < 2; half++) {
                    int n = nj * 2 + half;
                    #pragma unroll
                    for (int mi = 0; mi < 4; mi++)
                        imma16832(accC[mi][n], A2f[mi], &B1f[nj][half * 2]);
                }
        }
    }

    // ---- epilogue ----
    const float* bias_e = bias + (size_t)e * NC + c0;
    const float* sw_e = (WHICH ? g_sw2 : g_sw1) + (size_t)e * NC + c0;
    int colb = wn * 32 + (lane & 3) * 2;
    float2 bv[4], sv[4];
    #pragma unroll
    for (int n = 0; n < 4; n++) {
        bv[n] = *(const float2*)(bias_e + colb + n * 8);
        sv[n] = *(const float2*)(sw_e + colb + n * 8);
    }

    #pragma unroll
    for (int mi = 0; mi < 4; mi++) {
        #pragma unroll
        for (int half = 0; half < 2; half++) {
            int r = wm * 64 + mi * 16 + (lane >> 2) + half * 8;
            int a = s_a[r];
            if (a >= 0) {
                float sa = WHICH ? g_sh[a] : g_sx[a >> 1];
                float gte = WHICH ? g_route_g[a] : 0.0f;
                #pragma unroll
                for (int n = 0; n < 4; n++) {
                    float m0f = (float)accM[mi][n][half * 2 + 0]
                              + (float)accC[mi][n][half * 2 + 0] * (1.0f / 254.0f);
                    float m1f = (float)accM[mi][n][half * 2 + 1]
                              + (float)accC[mi][n][half * 2 + 1] * (1.0f / 254.0f);
                    float v0 = sa * sv[n].x * m0f + bv[n].x;
                    float v1 = sa * sv[n].y * m1f + bv[n].y;
                    size_t col = (size_t)c0 + colb + n * 8;
                    if (WHICH == 0) {
                        v0 = fmaxf(v0, 0.0f); v1 = fmaxf(v1, 0.0f);
                        *(float2*)(g_h + (size_t)a * HDIM + col) = make_float2(v0, v1);
                    } else {
                        float* yp = yout + (size_t)(a >> 1) * DDIM + col;
                        atomicAdd(yp,     gte * v0);
                        atomicAdd(yp + 1, gte * v1);
                    }
                }
            }
        }
    }
}

// ---------------- launch ----------------
extern "C" void kernel_launch(void* const* d_in, const int* in_sizes, int n_in,
                              void* d_out, int out_size) {
    (void)in_sizes; (void)n_in; (void)out_size;
    const float* x  = (const float*)d_in[0];
    const float* nz = (const float*)d_in[1];
    const float* wg = (const float*)d_in[2];
    const float* wn = (const float*)d_in[3];
    const float* W1 = (const float*)d_in[4];
    const float* b1 = (const float*)d_in[5];
    const float* W2 = (const float*)d_in[6];
    const float* b2 = (const float*)d_in[7];
    float* y = (float*)d_out;

    cudaFuncSetAttribute(moe_gemm_i8<0>, cudaFuncAttributeMaxDynamicSharedMemorySize, GEMM_SMEM);
    cudaFuncSetAttribute(moe_gemm_i8<1>, cudaFuncAttributeMaxDynamicSharedMemorySize, GEMM_SMEM);

    void *xq1, *xq2, *sx, *hq1, *hq2, *sh, *h;
    void *w1q1, *w1q2, *sw1, *w2q1, *w2q2, *sw2;
    cudaGetSymbolAddress(&xq1, g_xq1);  cudaGetSymbolAddress(&xq2, g_xq2);
    cudaGetSymbolAddress(&sx, g_sx);    cudaGetSymbolAddress(&h, g_h);
    cudaGetSymbolAddress(&hq1, g_hq1);  cudaGetSymbolAddress(&hq2, g_hq2);
    cudaGetSymbolAddress(&sh, g_sh);
    cudaGetSymbolAddress(&w1q1, g_w1q1); cudaGetSymbolAddress(&w1q2, g_w1q2);
    cudaGetSymbolAddress(&sw1, g_sw1);
    cudaGetSymbolAddress(&w2q1, g_w2q1); cudaGetSymbolAddress(&w2q2, g_w2q2);
    cudaGetSymbolAddress(&sw2, g_sw2);

    zero_counts<<<1, 32>>>();
    gate_kernel<<<NTOK / 8, 256>>>(x, nz, wg, wn);
    reduce_kernel<<<NEXP, 256>>>();
    loss_kernel<<<1, 1>>>(y + (size_t)NTOK * DDIM);

    quantize_rows<<<NTOK, 256>>>(x, (char*)xq1, (char*)xq2, (float*)sx, DDIM);
    quant_w_fused<<<dim3(HDIM / 32, NEXP), 256>>>(W1, (float*)sw1,
                                                  (char*)w1q1, (char*)w1q2, DDIM, HDIM);
    quant_w_fused<<<dim3(DDIM / 32, NEXP), 256>>>(W2, (float*)sw2,
                                                  (char*)w2q1, (char*)w2q2, HDIM, DDIM);

    moe_gemm_i8<0><<<dim3(HDIM / 128, NASSIGN / 128, NEXP), 256, GEMM_SMEM>>>(b1, nullptr);
    quantize_rows<<<NASSIGN, 256>>>((const float*)h, (char*)hq1, (char*)hq2, (float*)sh, HDIM);
    zero_y<<<NTOK * DDIM / 1024, 256>>>((float4*)y);
    moe_gemm_i8<1><<<dim3(DDIM / 128, NASSIGN / 128, NEXP), 256, GEMM_SMEM>>>(b2, y);
}

// round 8
// speedup vs baseline: 1.9927x; 1.9927x over previous
#include <cuda_runtime.h>
#include <cuda_fp16.h>
#include <math.h>
#include <stdint.h>

#define NTOK 8192
#define DDIM 1024
#define HDIM 4096
#define NEXP 8
#define NASSIGN (NTOK*2)

// ---------------- scratch (device globals; no allocation) ----------------
__device__ float  g_outb[(size_t)NASSIGN * DDIM];
__device__ float  g_loadc[NTOK * NEXP];
__device__ int    g_route_e[NASSIGN];
__device__ float  g_route_g[NASSIGN];
__device__ int    g_counts[NEXP];
__device__ int    g_perm[NEXP * NTOK];
__device__ float  g_load[NEXP];
__device__ float  g_imp[NEXP];
__device__ __half g_xh[(size_t)NTOK * DDIM];                // x fp16
__device__ __half g_hh[(size_t)NASSIGN * HDIM];             // hidden fp16
__device__ __half g_w1t[(size_t)NEXP * HDIM * DDIM];        // W1^T [e][n][k]
__device__ __half g_w2t[(size_t)NEXP * DDIM * HDIM];        // W2^T [e][n][k]

// ---------------- helpers ----------------
__device__ __forceinline__ uint32_t smem_to_u32(const void* p) {
    uint32_t a;
    asm("{ .reg .u64 t; cvta.to.shared.u64 t, %1; cvt.u32.u64 %0, t; }" : "=r"(a) : "l"(p));
    return a;
}
__device__ __forceinline__ void ldsm4(uint32_t* r, uint32_t a) {
    asm volatile("ldmatrix.sync.aligned.m8n8.x4.shared.b16 {%0,%1,%2,%3}, [%4];"
        : "=r"(r[0]), "=r"(r[1]), "=r"(r[2]), "=r"(r[3]) : "r"(a));
}
__device__ __forceinline__ void hmma16816(float* c, const uint32_t* a, const uint32_t* b) {
    asm volatile("mma.sync.aligned.m16n8k16.row.col.f32.f16.f16.f32 "
        "{%0,%1,%2,%3}, {%4,%5,%6,%7}, {%8,%9}, {%0,%1,%2,%3};"
        : "+f"(c[0]), "+f"(c[1]), "+f"(c[2]), "+f"(c[3])
        : "r"(a[0]), "r"(a[1]), "r"(a[2]), "r"(a[3]), "r"(b[0]), "r"(b[1]));
}
#define CP_ASYNC16(dst, src, sz) \
    asm volatile("cp.async.cg.shared.global [%0], [%1], 16, %2;" \
        :: "r"(dst), "l"(src), "r"(sz) : "memory")
#define CP_COMMIT() asm volatile("cp.async.commit_group;" ::: "memory")
#define CP_WAIT2()  asm volatile("cp.async.wait_group 2;" ::: "memory")

// ---------------- zero counters ----------------
__global__ void zero_counts() {
    if (threadIdx.x < NEXP) g_counts[threadIdx.x] = 0;
}

// ---------------- gating ----------------
__global__ void gate_kernel(const float* __restrict__ x,
                            const float* __restrict__ noise,
                            const float* __restrict__ wg,
                            const float* __restrict__ wn) {
    int warp = threadIdx.x >> 5;
    int lane = threadIdx.x & 31;
    int n = blockIdx.x * 8 + warp;
    if (n >= NTOK) return;
    float ac[8] = {0,0,0,0,0,0,0,0};
    float an[8] = {0,0,0,0,0,0,0,0};
    const float* xr = x + (size_t)n * DDIM;
    for (int d = lane; d < DDIM; d += 32) {
        float xv = xr[d];
        const float4* wgp = (const float4*)(wg + (size_t)d * 8);
        const float4* wnp = (const float4*)(wn + (size_t)d * 8);
        float4 gA = wgp[0], gB = wgp[1];
        float4 nA = wnp[0], nB = wnp[1];
        ac[0] += xv * gA.x; ac[1] += xv * gA.y; ac[2] += xv * gA.z; ac[3] += xv * gA.w;
        ac[4] += xv * gB.x; ac[5] += xv * gB.y; ac[6] += xv * gB.z; ac[7] += xv * gB.w;
        an[0] += xv * nA.x; an[1] += xv * nA.y; an[2] += xv * nA.z; an[3] += xv * nA.w;
        an[4] += xv * nB.x; an[5] += xv * nB.y; an[6] += xv * nB.z; an[7] += xv * nB.w;
    }
    #pragma unroll
    for (int off = 16; off; off >>= 1)
        #pragma unroll
        for (int e = 0; e < 8; e++) {
            ac[e] += __shfl_xor_sync(0xffffffffu, ac[e], off);
            an[e] += __shfl_xor_sync(0xffffffffu, an[e], off);
        }
    if (lane == 0) {
        float clean[8], sd[8], nz[8];
        #pragma unroll
        for (int e = 0; e < 8; e++) {
            clean[e] = ac[e];
            float z = an[e];
            float sp = fmaxf(z, 0.0f) + log1pf(expf(-fabsf(z)));
            sd[e] = sp + 0.01f;
            nz[e] = clean[e] + noise[(size_t)n * 8 + e] * sd[e];
        }
        int i0 = 0, i1 = -1;
        float v0 = nz[0], v1 = -INFINITY, v2 = -INFINITY;
        #pragma unroll
        for (int e = 1; e < 8; e++) {
            float v = nz[e];
            if (v > v0)      { v2 = v1; v1 = v0; i1 = i0; v0 = v; i0 = e; }
            else if (v > v1) { v2 = v1; v1 = v;  i1 = e; }
            else if (v > v2) { v2 = v; }
        }
        float t = expf(v1 - v0);
        float gate0 = 1.0f / (1.0f + t);
        float gate1 = t / (1.0f + t);
        #pragma unroll
        for (int e = 0; e < 8; e++) {
            bool is_in = nz[e] > v2;
            float thr = is_in ? v2 : v1;
            g_loadc[(size_t)n * 8 + e] = normcdff((clean[e] - thr) / sd[e]);
        }
        g_route_e[2 * n]     = i0;  g_route_g[2 * n]     = gate0;
        g_route_e[2 * n + 1] = i1;  g_route_g[2 * n + 1] = gate1;
        int p0 = atomicAdd(&g_counts[i0], 1);
        g_perm[i0 * NTOK + p0] = 2 * n;
        int p1 = atomicAdd(&g_counts[i1], 1);
        g_perm[i1 * NTOK + p1] = 2 * n + 1;
    }
}

__global__ void reduce_kernel() {
    int e = blockIdx.x;
    int t = threadIdx.x;
    float sl = 0.0f, si = 0.0f;
    for (int n = t; n < NTOK; n += 256) sl += g_loadc[(size_t)n * 8 + e];
    for (int a = t; a < NASSIGN; a += 256)
        if (g_route_e[a] == e) si += g_route_g[a];
    __shared__ float shl[256], shi[256];
    shl[t] = sl; shi[t] = si;
    __syncthreads();
    for (int off = 128; off; off >>= 1) {
        if (t < off) { shl[t] += shl[t + off]; shi[t] += shi[t + off]; }
        __syncthreads();
    }
    if (t == 0) { g_load[e] = shl[0]; g_imp[e] = shi[0]; }
}

__global__ void loss_kernel(float* __restrict__ out) {
    if (threadIdx.x != 0 || blockIdx.x != 0) return;
    float mi = 0.0f, ml = 0.0f;
    for (int e = 0; e < NEXP; e++) { mi += g_imp[e]; ml += g_load[e]; }
    mi *= (1.0f / NEXP); ml *= (1.0f / NEXP);
    float vi = 0.0f, vl = 0.0f;
    for (int e = 0; e < NEXP; e++) {
        float di = g_imp[e] - mi;  vi += di * di;
        float dl = g_load[e] - ml; vl += dl * dl;
    }
    vi *= (1.0f / (NEXP - 1)); vl *= (1.0f / (NEXP - 1));
    out[0] = (vi / (mi * mi + 1e-10f) + vl / (ml * ml + 1e-10f)) * 0.01f;
}

// ---------------- x fp32 -> fp16 ----------------
__global__ void convert_x(const float4* __restrict__ src, uint2* __restrict__ dst, size_t n4) {
    size_t stride = (size_t)gridDim.x * blockDim.x;
    for (size_t i = (size_t)blockIdx.x * blockDim.x + threadIdx.x; i < n4; i += stride) {
        float4 v = src[i];
        __half2 a = __floats2half2_rn(v.x, v.y);
        __half2 b = __floats2half2_rn(v.z, v.w);
        uint2 o;
        memcpy(&o.x, &a, 4); memcpy(&o.y, &b, 4);
        dst[i] = o;
    }
}

// ---------------- weight fp32 [e][K][N] -> fp16 transposed [e][N][K] ----------------
__global__ void convert_w(const float* __restrict__ W, __half* __restrict__ Wt,
                          int K, int N) {
    __shared__ float tile[32][33];
    int e = blockIdx.z;
    int k0 = blockIdx.x * 32, n0 = blockIdx.y * 32;
    int tx = threadIdx.x, ty = threadIdx.y;
    const float* Wp = W + (size_t)e * K * N;
    #pragma unroll
    for (int i = 0; i < 4; i++)
        tile[ty + 8 * i][tx] = Wp[(size_t)(k0 + ty + 8 * i) * N + n0 + tx];
    __syncthreads();
    #pragma unroll
    for (int i = 0; i < 4; i++) {
        float v = tile[tx][ty + 8 * i];
        Wt[((size_t)e * N + n0 + ty + 8 * i) * K + k0 + tx] = __float2half_rn(v);
    }
}

// ---------------- fp16 grouped expert GEMM ----------------
// CTA 128x256, k-chunk 64, 8 warps (2m x 4n), warp tile 64x64, 4-stage pipe.
// Stage: A@0 (16K, 128 rows x 128B) | B@16384 (32K, 256 rows x 128B) = 48KB.
// Row swizzle: 128B rows, chunk c(16B) stored at c ^ (row & 7)  -> conflict-free
// for both cp.async stores and ldmatrix reads.
#define STG 49152
#define NSTAGE 4
#define GEMM_SMEM (NSTAGE * STG)

template <int WHICH>
__global__ __launch_bounds__(256, 1) void moe_gemm_f16(const float* __restrict__ bias) {
    constexpr int KD = WHICH ? HDIM : DDIM;
    constexpr int NC = WHICH ? DDIM : HDIM;
    constexpr int NST = KD / 64;

    const int e = blockIdx.z;
    const int count = g_counts[e];
    const int m0 = blockIdx.y * 128;
    if (m0 >= count) return;
    const int c0 = blockIdx.x * 256;

    extern __shared__ char smem[];
    __shared__ int s_a[128];
    const uint32_t sb = smem_to_u32(smem);
    const int t = threadIdx.x;
    const int lane = t & 31, wid = t >> 5;
    const int wm = wid & 1, wn = wid >> 1;

    if (t < 128) {
        int m = m0 + t;
        s_a[t] = (m < count) ? g_perm[e * NTOK + m] : -1;
    }
    __syncthreads();

    const char* Ab = (const char*)(WHICH ? g_hh : g_xh);
    const char* Bb = (const char*)((WHICH ? g_w2t : g_w1t) + ((size_t)e * NC + c0) * KD);

    // A: 128 rows x 128B/stage -> 1024 chunks, 4 per thread
    const char* sA[4]; uint32_t adst[4]; int asz[4];
    #pragma unroll
    for (int i = 0; i < 4; i++) {
        int u = t + 256 * i;
        int r = u >> 3, c = u & 7;
        int a = s_a[r];
        int rowi = (a < 0) ? 0 : (WHICH ? a : (a >> 1));
        sA[i] = Ab + ((size_t)rowi * KD) * 2 + c * 16;
        asz[i] = (a < 0) ? 0 : 16;
        adst[i] = r * 128 + (((uint32_t)(c ^ (r & 7))) << 4);
    }
    // B: 256 rows x 128B/stage -> 2048 chunks, 8 per thread
    const char* sB[8]; uint32_t bdst[8];
    #pragma unroll
    for (int i = 0; i < 8; i++) {
        int u = t + 256 * i;
        int r = u >> 3, c = u & 7;
        sB[i] = Bb + ((size_t)r * KD) * 2 + c * 16;
        bdst[i] = 16384u + r * 128 + (((uint32_t)(c ^ (r & 7))) << 4);
    }

    auto load_stage = [&](int s) {
        uint32_t base = sb + (uint32_t)(s & (NSTAGE - 1)) * STG;
        int koff = s * 128;   // 64 fp16 = 128 bytes
        #pragma unroll
        for (int i = 0; i < 4; i++)
            CP_ASYNC16(base + adst[i], sA[i] + koff, asz[i]);
        #pragma unroll
        for (int i = 0; i < 8; i++)
            CP_ASYNC16(base + bdst[i], sB[i] + koff, 16);
        CP_COMMIT();
    };

    // ldsm offsets (ks toggles via XOR (ks<<5))
    uint32_t aoff[4];
    #pragma unroll
    for (int mi = 0; mi < 4; mi++) {
        int row = wm * 64 + mi * 16 + (lane & 15);
        int c = lane >> 4;                       // 0,1 = k-halves of k16
        aoff[mi] = row * 128 + (((uint32_t)(c ^ (row & 7))) << 4);
    }
    uint32_t boff[4];
    #pragma unroll
    for (int p = 0; p < 4; p++) {
        int g = lane >> 3;
        int row = wn * 64 + p * 16 + (g >> 1) * 8 + (lane & 7);
        int c = g & 1;
        boff[p] = 16384u + row * 128 + (((uint32_t)(c ^ (row & 7))) << 4);
    }

    float acc[4][8][4];
    #pragma unroll
    for (int i = 0; i < 4; i++)
        #pragma unroll
        for (int j = 0; j < 8; j++)
            #pragma unroll
            for (int k = 0; k < 4; k++) acc[i][j][k] = 0.0f;

    load_stage(0);
    load_stage(1);
    load_stage(2);

    for (int s = 0; s < NST; s++) {
        CP_WAIT2();
        __syncthreads();
        if (s + 3 < NST) load_stage(s + 3);
        else CP_COMMIT();
        uint32_t ab = sb + (uint32_t)(s & (NSTAGE - 1)) * STG;
        #pragma unroll
        for (int ks = 0; ks < 4; ks++) {
            const uint32_t kx = (uint32_t)ks << 5;
            uint32_t Af[4][4], Bf[4][4];
            #pragma unroll
            for (int mi = 0; mi < 4; mi++) ldsm4(Af[mi], ab + (aoff[mi] ^ kx));
            #pragma unroll
            for (int p = 0; p < 4; p++)    ldsm4(Bf[p], ab + (boff[p] ^ kx));
            #pragma unroll
            for (int p = 0; p < 4; p++)
                #pragma unroll
                for (int half = 0; half < 2; half++) {
                    int n = p * 2 + half;
                    #pragma unroll
                    for (int mi = 0; mi < 4; mi++)
                        hmma16816(acc[mi][n], Af[mi], &Bf[p][half * 2]);
                }
        }
    }

    // ---- epilogue ----
    const float* bias_e = bias + (size_t)e * NC + c0;
    int colb = wn * 64 + (lane & 3) * 2;
    float2 bv[8];
    #pragma unroll
    for (int n = 0; n < 8; n++) bv[n] = *(const float2*)(bias_e + colb + n * 8);

    #pragma unroll
    for (int mi = 0; mi < 4; mi++) {
        #pragma unroll
        for (int half = 0; half < 2; half++) {
            int r = wm * 64 + mi * 16 + (lane >> 2) + half * 8;
            int a = s_a[r];
            if (a >= 0) {
                #pragma unroll
                for (int n = 0; n < 8; n++) {
                    float v0 = acc[mi][n][half * 2 + 0] + bv[n].x;
                    float v1 = acc[mi][n][half * 2 + 1] + bv[n].y;
                    size_t col = (size_t)c0 + colb + n * 8;
                    if (WHICH == 0) {
                        v0 = fmaxf(v0, 0.0f); v1 = fmaxf(v1, 0.0f);
                        __half2 hv = __floats2half2_rn(v0, v1);
                        *(__half2*)(g_hh + (size_t)a * HDIM + col) = hv;
                    } else {
                        *(float2*)(g_outb + (size_t)a * DDIM + col) = make_float2(v0, v1);
                    }
                }
            }
        }
    }
}

// ---------------- combine ----------------
__global__ void combine_kernel(float* __restrict__ y) {
    int n = blockIdx.x;
    int t = threadIdx.x;
    float gate0 = g_route_g[2 * n];
    float gate1 = g_route_g[2 * n + 1];
    const float4* o0 = (const float4*)(g_outb + (size_t)(2 * n) * DDIM);
    const float4* o1 = (const float4*)(g_outb + (size_t)(2 * n + 1) * DDIM);
    float4* yp = (float4*)(y + (size_t)n * DDIM);
    float4 a = o0[t], b = o1[t];
    yp[t] = make_float4(gate0 * a.x + gate1 * b.x,
                        gate0 * a.y + gate1 * b.y,
                        gate0 * a.z + gate1 * b.z,
                        gate0 * a.w + gate1 * b.w);
}

// ---------------- launch ----------------
extern "C" void kernel_launch(void* const* d_in, const int* in_sizes, int n_in,
                              void* d_out, int out_size) {
    (void)in_sizes; (void)n_in; (void)out_size;
    const float* x  = (const float*)d_in[0];
    const float* nz = (const float*)d_in[1];
    const float* wg = (const float*)d_in[2];
    const float* wn = (const float*)d_in[3];
    const float* W1 = (const float*)d_in[4];
    const float* b1 = (const float*)d_in[5];
    const float* W2 = (const float*)d_in[6];
    const float* b2 = (const float*)d_in[7];
    float* y = (float*)d_out;

    cudaFuncSetAttribute(moe_gemm_f16<0>, cudaFuncAttributeMaxDynamicSharedMemorySize, GEMM_SMEM);
    cudaFuncSetAttribute(moe_gemm_f16<1>, cudaFuncAttributeMaxDynamicSharedMemorySize, GEMM_SMEM);

    void *xh, *w1t, *w2t;
    cudaGetSymbolAddress(&xh, g_xh);
    cudaGetSymbolAddress(&w1t, g_w1t);
    cudaGetSymbolAddress(&w2t, g_w2t);

    zero_counts<<<1, 32>>>();
    gate_kernel<<<NTOK / 8, 256>>>(x, nz, wg, wn);
    reduce_kernel<<<NEXP, 256>>>();
    loss_kernel<<<1, 1>>>(y + (size_t)NTOK * DDIM);

    convert_x<<<1024, 256>>>((const float4*)x, (uint2*)xh, (size_t)NTOK * DDIM / 4);
    convert_w<<<dim3(DDIM / 32, HDIM / 32, NEXP), dim3(32, 8)>>>(W1, (__half*)w1t, DDIM, HDIM);
    convert_w<<<dim3(HDIM / 32, DDIM / 32, NEXP), dim3(32, 8)>>>(W2, (__half*)w2t, HDIM, DDIM);

    moe_gemm_f16<0><<<dim3(HDIM / 256, NASSIGN / 128, NEXP), 256, GEMM_SMEM>>>(b1);
    moe_gemm_f16<1><<<dim3(DDIM / 256, NASSIGN / 128, NEXP), 256, GEMM_SMEM>>>(b2);
    combine_kernel<<<NTOK, 256>>>(y);
}